// round 6
// baseline (speedup 1.0000x reference)
#include <cuda_runtime.h>

// BayesianMetaPosterior: scalar loss from two reductions.
//   S_sq  = sum(metamean^2)    over D elements
//   S_lg2 = sum(log2(fishers)) over M*D elements (scaled by ln2 at the end)
//   loss  = (M-1)*( S_sq/(2*sigma^2) + D*(log(sigma)+0.5*log(2pi)) )
//         + ( -0.5*M*D*log(2pi) + 0.5*ln2*S_lg2 )
// `means` (d_in[1]) is mathematically unused (Mahalanobis term == 0).
//
// Warp-level work stealing over contiguous 4KB chunks (256 float4 = one
// unroll-8 LDG.128 batch per warp). The steal atomic for the NEXT chunk is
// issued before processing the current one (fire-and-forget; shfl broadcast
// deferred past the compute), so steal latency is fully hidden. No barriers
// in the hot loop. Last-finished block finalizes.

#define NB   740            // 148 SMs * 5 CTAs (one wave @ 256 thr)
#define NT   256
#define CQ   256            // float4 per warp-chunk = 4 KB

__device__ double g_part_sq[NB];
__device__ double g_part_log[NB];
__device__ unsigned int g_chunk_ctr;    // zero-init; self-resets each run
__device__ unsigned int g_done_count;   // zero-init; self-resets each run

__device__ __forceinline__ double block_reduce(double v) {
    __shared__ double sm[NT / 32];
    #pragma unroll
    for (int off = 16; off > 0; off >>= 1)
        v += __shfl_down_sync(0xFFFFFFFFu, v, off);
    int lane = threadIdx.x & 31, warp = threadIdx.x >> 5;
    if (lane == 0) sm[warp] = v;
    __syncthreads();
    if (warp == 0) {
        v = (lane < NT / 32) ? sm[lane] : 0.0;
        #pragma unroll
        for (int off = 4; off > 0; off >>= 1)
            v += __shfl_down_sync(0xFFFFFFFFu, v, off);
    }
    return v;  // valid in thread 0
}

__global__ __launch_bounds__(NT, 5)
void bmp_kernel(const float* __restrict__ metamean,
                const float* __restrict__ fishers,
                long long D, long long MD, int M,
                float* __restrict__ out, int out_size)
{
    const float4* __restrict__ mm4 = reinterpret_cast<const float4*>(metamean);
    const float4* __restrict__ ff4 = reinterpret_cast<const float4*>(fishers);
    const long long n4m = D >> 2;
    const long long n4f = MD >> 2;

    const unsigned int nCm = (unsigned int)((n4m + CQ - 1) / CQ);
    const unsigned int nCf = (unsigned int)((n4f + CQ - 1) / CQ);
    const unsigned int nC  = nCm + nCf;

    const int lane = threadIdx.x & 31;

    float sq0 = 0.f, sq1 = 0.f, sq2 = 0.f, sq3 = 0.f;
    float lg0 = 0.f, lg1 = 0.f, lg2_ = 0.f, lg3 = 0.f;

    // first steal (latency exposed once per warp only)
    unsigned int c_raw = 0;
    if (lane == 0) c_raw = atomicAdd(&g_chunk_ctr, 1u);
    unsigned int c = __shfl_sync(0xFFFFFFFFu, c_raw, 0);

    while (c < nC) {
        // fire-and-forget steal of the NEXT chunk; broadcast deferred
        unsigned int cn_raw = 0;
        if (lane == 0) cn_raw = atomicAdd(&g_chunk_ctr, 1u);

        const bool is_fish = (c >= nCm);
        const float4* __restrict__ base = is_fish ? ff4 : mm4;
        const long long hi = is_fish ? n4f : n4m;
        const long long q0 = (long long)(is_fish ? c - nCm : c) * CQ + lane;

        if (q0 + 7 * 32 < hi) {
            // full chunk: 8 independent LDG.128, front-batched
            float4 v0 = __ldcs(base + q0);
            float4 v1 = __ldcs(base + q0 + 1 * 32);
            float4 v2 = __ldcs(base + q0 + 2 * 32);
            float4 v3 = __ldcs(base + q0 + 3 * 32);
            float4 v4 = __ldcs(base + q0 + 4 * 32);
            float4 v5 = __ldcs(base + q0 + 5 * 32);
            float4 v6 = __ldcs(base + q0 + 6 * 32);
            float4 v7 = __ldcs(base + q0 + 7 * 32);
            if (is_fish) {
                lg0 += __log2f(v0.x) + __log2f(v0.y) + __log2f(v0.z) + __log2f(v0.w)
                     + __log2f(v4.x) + __log2f(v4.y) + __log2f(v4.z) + __log2f(v4.w);
                lg1 += __log2f(v1.x) + __log2f(v1.y) + __log2f(v1.z) + __log2f(v1.w)
                     + __log2f(v5.x) + __log2f(v5.y) + __log2f(v5.z) + __log2f(v5.w);
                lg2_ += __log2f(v2.x) + __log2f(v2.y) + __log2f(v2.z) + __log2f(v2.w)
                     + __log2f(v6.x) + __log2f(v6.y) + __log2f(v6.z) + __log2f(v6.w);
                lg3 += __log2f(v3.x) + __log2f(v3.y) + __log2f(v3.z) + __log2f(v3.w)
                     + __log2f(v7.x) + __log2f(v7.y) + __log2f(v7.z) + __log2f(v7.w);
            } else {
                sq0 += v0.x * v0.x + v0.y * v0.y + v0.z * v0.z + v0.w * v0.w
                     + v4.x * v4.x + v4.y * v4.y + v4.z * v4.z + v4.w * v4.w;
                sq1 += v1.x * v1.x + v1.y * v1.y + v1.z * v1.z + v1.w * v1.w
                     + v5.x * v5.x + v5.y * v5.y + v5.z * v5.z + v5.w * v5.w;
                sq2 += v2.x * v2.x + v2.y * v2.y + v2.z * v2.z + v2.w * v2.w
                     + v6.x * v6.x + v6.y * v6.y + v6.z * v6.z + v6.w * v6.w;
                sq3 += v3.x * v3.x + v3.y * v3.y + v3.z * v3.z + v3.w * v3.w
                     + v7.x * v7.x + v7.y * v7.y + v7.z * v7.z + v7.w * v7.w;
            }
        } else {
            // partial (last) chunk of a region: guarded
            #pragma unroll
            for (int u = 0; u < 8; u++) {
                long long qq = q0 + (long long)u * 32;
                if (qq < hi) {
                    float4 v = __ldcs(base + qq);
                    if (is_fish)
                        lg0 += __log2f(v.x) + __log2f(v.y)
                             + __log2f(v.z) + __log2f(v.w);
                    else
                        sq0 += v.x * v.x + v.y * v.y + v.z * v.z + v.w * v.w;
                }
            }
        }

        // by now the steal atomic has long returned: broadcast it
        c = __shfl_sync(0xFFFFFFFFu, cn_raw, 0);
    }

    double asq = ((double)sq0 + (double)sq1) + ((double)sq2 + (double)sq3);
    double alg = ((double)lg0 + (double)lg1) + ((double)lg2_ + (double)lg3);
    asq = block_reduce(asq);
    __syncthreads();
    alg = block_reduce(alg);

    __shared__ bool s_last;
    if (threadIdx.x == 0) {
        g_part_sq[blockIdx.x]  = asq;
        g_part_log[blockIdx.x] = alg;
        __threadfence();
        unsigned int prev = atomicAdd(&g_done_count, 1u);
        s_last = (prev == NB - 1);
    }
    __syncthreads();

    // ---- last block to finish performs the final reduction ----
    if (s_last) {
        double a = 0.0, b = 0.0;
        for (int k = threadIdx.x; k < NB; k += NT) {
            a += g_part_sq[k];
            b += g_part_log[k];
        }
        a = block_reduce(a);
        __syncthreads();
        b = block_reduce(b);
        if (threadIdx.x == 0) {
            // scalar remainders (none when D,MD % 4 == 0; kept for safety)
            for (long long j = (n4m << 2); j < D;  j++) {
                double v = (double)metamean[j];
                a += v * v;
            }
            for (long long j = (n4f << 2); j < MD; j++)
                b += (double)__log2f(fishers[j]);

            const double log2pi = 1.8378770664093453;      // log(2*pi)
            const double logsig = -2.3025850929940456840;  // log(0.1)
            const double inv2s2 = 50.0;                    // 1/(2*0.1^2)
            const double ln2    = 0.6931471805599453;      // log2 -> ln
            double prior_term = (double)(M - 1) *
                (inv2s2 * a + (double)D * (logsig + 0.5 * log2pi));
            double post_term = -0.5 * (double)M * (double)D * log2pi
                               + 0.5 * ln2 * b;
            float loss = (float)(prior_term + post_term);
            for (int k = 0; k < out_size; k++) out[k] = loss;
            g_chunk_ctr  = 0;      // self-reset for next graph replay
            g_done_count = 0;
        }
    }
}

extern "C" void kernel_launch(void* const* d_in, const int* in_sizes, int n_in,
                              void* d_out, int out_size)
{
    const float* metamean = (const float*)d_in[0];
    // d_in[1] = means: unused (Mahalanobis term is identically zero)
    const float* fishers  = (const float*)d_in[2];

    const long long D  = (long long)in_sizes[0];
    const long long MD = (long long)in_sizes[2];
    const int M = (int)(MD / D);

    bmp_kernel<<<NB, NT>>>(metamean, fishers, D, MD, M,
                           (float*)d_out, out_size);
}

// round 7
// speedup vs baseline: 1.5720x; 1.5720x over previous
#include <cuda_runtime.h>

// BayesianMetaPosterior: scalar loss from two reductions.
//   S_sq  = sum(metamean^2)    over D elements
//   S_lg2 = sum(log2(fishers)) over M*D elements (scaled by ln2 at the end)
//   loss  = (M-1)*( S_sq/(2*sigma^2) + D*(log(sigma)+0.5*log(2pi)) )
//         + ( -0.5*M*D*log(2pi) + 0.5*ln2*S_lg2 )
// `means` (d_in[1]) is mathematically unused (Mahalanobis term == 0).
//
// Static HOMOGENEOUS slabs: every block owns a contiguous 1/NB slice of BOTH
// arrays, so byte count AND MUFU work are identical across blocks (no
// meta/fisher finish-time asymmetry). Unroll-8 front-batched LDG.128
// streaming loads, float accumulators, double across threads only.
// No dynamic work distribution (single-counter atomics serialize on B300).

#define NB   740            // 148 SMs * 5 CTAs (one wave @ 256 thr)
#define NT   256

__device__ double g_part_sq[NB];
__device__ double g_part_log[NB];
__device__ unsigned int g_done_count;   // zero-init; self-resets each run

__device__ __forceinline__ double block_reduce(double v) {
    __shared__ double sm[NT / 32];
    #pragma unroll
    for (int off = 16; off > 0; off >>= 1)
        v += __shfl_down_sync(0xFFFFFFFFu, v, off);
    int lane = threadIdx.x & 31, warp = threadIdx.x >> 5;
    if (lane == 0) sm[warp] = v;
    __syncthreads();
    if (warp == 0) {
        v = (lane < NT / 32) ? sm[lane] : 0.0;
        #pragma unroll
        for (int off = 4; off > 0; off >>= 1)
            v += __shfl_down_sync(0xFFFFFFFFu, v, off);
    }
    return v;  // valid in thread 0
}

// slab boundary for block b over n quads, 32-quad (512B) aligned starts
__device__ __forceinline__ long long slab_edge(int b, long long n) {
    long long e = (long long)b * n / NB;
    return e & ~31LL;
}

__global__ __launch_bounds__(NT, 5)
void bmp_kernel(const float* __restrict__ metamean,
                const float* __restrict__ fishers,
                long long D, long long MD, int M,
                float* __restrict__ out, int out_size)
{
    const float4* __restrict__ mm4 = reinterpret_cast<const float4*>(metamean);
    const float4* __restrict__ ff4 = reinterpret_cast<const float4*>(fishers);
    const long long n4m = D >> 2;    // D  % 4 == 0 here
    const long long n4f = MD >> 2;   // MD % 4 == 0 here
    const int b = (int)blockIdx.x;

    float sq0 = 0.f, sq1 = 0.f, sq2 = 0.f, sq3 = 0.f;
    float lg0 = 0.f, lg1 = 0.f, lg2a = 0.f, lg3 = 0.f;

    // ---- fisher slab (MUFU-heavy; identical share for every block) ----
    {
        const long long qb = slab_edge(b, n4f);
        const long long qe = (b == NB - 1) ? n4f : slab_edge(b + 1, n4f);
        long long q = qb + threadIdx.x;
        for (; q + 7 * NT < qe; q += 8 * NT) {
            float4 v0 = __ldcs(ff4 + q);
            float4 v1 = __ldcs(ff4 + q + 1 * NT);
            float4 v2 = __ldcs(ff4 + q + 2 * NT);
            float4 v3 = __ldcs(ff4 + q + 3 * NT);
            float4 v4 = __ldcs(ff4 + q + 4 * NT);
            float4 v5 = __ldcs(ff4 + q + 5 * NT);
            float4 v6 = __ldcs(ff4 + q + 6 * NT);
            float4 v7 = __ldcs(ff4 + q + 7 * NT);
            lg0 += __log2f(v0.x) + __log2f(v0.y) + __log2f(v0.z) + __log2f(v0.w)
                 + __log2f(v4.x) + __log2f(v4.y) + __log2f(v4.z) + __log2f(v4.w);
            lg1 += __log2f(v1.x) + __log2f(v1.y) + __log2f(v1.z) + __log2f(v1.w)
                 + __log2f(v5.x) + __log2f(v5.y) + __log2f(v5.z) + __log2f(v5.w);
            lg2a += __log2f(v2.x) + __log2f(v2.y) + __log2f(v2.z) + __log2f(v2.w)
                 + __log2f(v6.x) + __log2f(v6.y) + __log2f(v6.z) + __log2f(v6.w);
            lg3 += __log2f(v3.x) + __log2f(v3.y) + __log2f(v3.z) + __log2f(v3.w)
                 + __log2f(v7.x) + __log2f(v7.y) + __log2f(v7.z) + __log2f(v7.w);
        }
        for (; q < qe; q += NT) {
            float4 v = __ldcs(ff4 + q);
            lg0 += __log2f(v.x) + __log2f(v.y) + __log2f(v.z) + __log2f(v.w);
        }
        if (b == NB - 1) {
            for (long long j = (n4f << 2) + threadIdx.x; j < MD; j += NT)
                lg0 += __log2f(__ldg(&fishers[j]));
        }
    }

    // ---- metamean slab ----
    {
        const long long qb = slab_edge(b, n4m);
        const long long qe = (b == NB - 1) ? n4m : slab_edge(b + 1, n4m);
        long long q = qb + threadIdx.x;
        for (; q + 7 * NT < qe; q += 8 * NT) {
            float4 v0 = __ldcs(mm4 + q);
            float4 v1 = __ldcs(mm4 + q + 1 * NT);
            float4 v2 = __ldcs(mm4 + q + 2 * NT);
            float4 v3 = __ldcs(mm4 + q + 3 * NT);
            float4 v4 = __ldcs(mm4 + q + 4 * NT);
            float4 v5 = __ldcs(mm4 + q + 5 * NT);
            float4 v6 = __ldcs(mm4 + q + 6 * NT);
            float4 v7 = __ldcs(mm4 + q + 7 * NT);
            sq0 += v0.x * v0.x + v0.y * v0.y + v0.z * v0.z + v0.w * v0.w
                 + v4.x * v4.x + v4.y * v4.y + v4.z * v4.z + v4.w * v4.w;
            sq1 += v1.x * v1.x + v1.y * v1.y + v1.z * v1.z + v1.w * v1.w
                 + v5.x * v5.x + v5.y * v5.y + v5.z * v5.z + v5.w * v5.w;
            sq2 += v2.x * v2.x + v2.y * v2.y + v2.z * v2.z + v2.w * v2.w
                 + v6.x * v6.x + v6.y * v6.y + v6.z * v6.z + v6.w * v6.w;
            sq3 += v3.x * v3.x + v3.y * v3.y + v3.z * v3.z + v3.w * v3.w
                 + v7.x * v7.x + v7.y * v7.y + v7.z * v7.z + v7.w * v7.w;
        }
        for (; q < qe; q += NT) {
            float4 v = __ldcs(mm4 + q);
            sq0 += v.x * v.x + v.y * v.y + v.z * v.z + v.w * v.w;
        }
        if (b == NB - 1) {
            for (long long j = (n4m << 2) + threadIdx.x; j < D; j += NT) {
                float v = __ldg(&metamean[j]);
                sq0 += v * v;
            }
        }
    }

    double asq = ((double)sq0 + (double)sq1) + ((double)sq2 + (double)sq3);
    double alg = ((double)lg0 + (double)lg1) + ((double)lg2a + (double)lg3);
    asq = block_reduce(asq);
    __syncthreads();
    alg = block_reduce(alg);

    __shared__ bool s_last;
    if (threadIdx.x == 0) {
        g_part_sq[blockIdx.x]  = asq;
        g_part_log[blockIdx.x] = alg;
        __threadfence();
        unsigned int prev = atomicAdd(&g_done_count, 1u);
        s_last = (prev == NB - 1);
    }
    __syncthreads();

    // ---- last block to finish performs the final reduction ----
    if (s_last) {
        double a = 0.0, bsum = 0.0;
        for (int k = threadIdx.x; k < NB; k += NT) {
            a    += g_part_sq[k];
            bsum += g_part_log[k];
        }
        a = block_reduce(a);
        __syncthreads();
        bsum = block_reduce(bsum);
        if (threadIdx.x == 0) {
            const double log2pi = 1.8378770664093453;      // log(2*pi)
            const double logsig = -2.3025850929940456840;  // log(0.1)
            const double inv2s2 = 50.0;                    // 1/(2*0.1^2)
            const double ln2    = 0.6931471805599453;      // log2 -> ln
            double prior_term = (double)(M - 1) *
                (inv2s2 * a + (double)D * (logsig + 0.5 * log2pi));
            double post_term = -0.5 * (double)M * (double)D * log2pi
                               + 0.5 * ln2 * bsum;
            float loss = (float)(prior_term + post_term);
            for (int k = 0; k < out_size; k++) out[k] = loss;
            g_done_count = 0;      // self-reset for next graph replay
        }
    }
}

extern "C" void kernel_launch(void* const* d_in, const int* in_sizes, int n_in,
                              void* d_out, int out_size)
{
    const float* metamean = (const float*)d_in[0];
    // d_in[1] = means: unused (Mahalanobis term is identically zero)
    const float* fishers  = (const float*)d_in[2];

    const long long D  = (long long)in_sizes[0];
    const long long MD = (long long)in_sizes[2];
    const int M = (int)(MD / D);

    bmp_kernel<<<NB, NT>>>(metamean, fishers, D, MD, M,
                           (float*)d_out, out_size);
}

// round 8
// speedup vs baseline: 1.6181x; 1.0293x over previous
#include <cuda_runtime.h>

// BayesianMetaPosterior: scalar loss from two reductions.
//   S_sq  = sum(metamean^2)    over D elements
//   S_lg2 = sum(log2(fishers)) over M*D elements (scaled by ln2 at the end)
//   loss  = (M-1)*( S_sq/(2*sigma^2) + D*(log(sigma)+0.5*log(2pi)) )
//         + ( -0.5*M*D*log(2pi) + 0.5*ln2*S_lg2 )
// `means` (d_in[1]) is mathematically unused (Mahalanobis term == 0).
//
// 148 blocks x 1024 threads = ONE CTA per SM, ONE contiguous ~2.3MB slab per
// block (148 sequential DRAM streams total -> max row/page locality).
// Dedicated split 37 meta : 111 fisher (exact 1:3 byte ratio). Unroll-8
// front-batched LDG.128 streaming loads, float accumulators, double across
// threads only. Last-finished block finalizes. No dynamic distribution
// (single-counter atomics serialize on B300; proven R5/R6).

#define NB_M 37
#define NB_F 111
#define NB   (NB_M + NB_F)   // 148 = one block per SM
#define NT   1024

__device__ double g_part_sq[NB_M];
__device__ double g_part_log[NB_F];
__device__ unsigned int g_done_count;   // zero-init; self-resets each run

__device__ __forceinline__ double block_reduce(double v) {
    __shared__ double sm[NT / 32];
    #pragma unroll
    for (int off = 16; off > 0; off >>= 1)
        v += __shfl_down_sync(0xFFFFFFFFu, v, off);
    int lane = threadIdx.x & 31, warp = threadIdx.x >> 5;
    if (lane == 0) sm[warp] = v;
    __syncthreads();
    if (warp == 0) {
        v = (lane < NT / 32) ? sm[lane] : 0.0;
        #pragma unroll
        for (int off = 16; off > 0; off >>= 1)
            v += __shfl_down_sync(0xFFFFFFFFu, v, off);
    }
    return v;  // valid in thread 0
}

__global__ __launch_bounds__(NT, 1)
void bmp_kernel(const float* __restrict__ metamean,
                const float* __restrict__ fishers,
                long long D, long long MD, int M,
                float* __restrict__ out, int out_size)
{
    const bool is_fish = (blockIdx.x >= NB_M);
    const float* __restrict__ srcf = is_fish ? fishers : metamean;
    const float4* __restrict__ base = reinterpret_cast<const float4*>(srcf);
    const long long nElem = is_fish ? MD : D;
    const long long n4    = nElem >> 2;
    const int  bid = is_fish ? (int)blockIdx.x - NB_M : (int)blockIdx.x;
    const int  nb  = is_fish ? NB_F : NB_M;

    // contiguous slab of quads for this block, 32-quad aligned starts
    long long qb = ((long long)bid * n4 / nb) & ~31LL;
    long long qe = (bid == nb - 1) ? n4 : (((long long)(bid + 1) * n4 / nb) & ~31LL);

    float a0 = 0.f, a1 = 0.f, a2 = 0.f, a3 = 0.f;
    float a4 = 0.f, a5 = 0.f, a6 = 0.f, a7 = 0.f;

    long long q = qb + threadIdx.x;

    if (is_fish) {
        for (; q + 7 * NT < qe; q += 8 * NT) {
            float4 v0 = __ldcs(base + q);
            float4 v1 = __ldcs(base + q + 1 * NT);
            float4 v2 = __ldcs(base + q + 2 * NT);
            float4 v3 = __ldcs(base + q + 3 * NT);
            float4 v4 = __ldcs(base + q + 4 * NT);
            float4 v5 = __ldcs(base + q + 5 * NT);
            float4 v6 = __ldcs(base + q + 6 * NT);
            float4 v7 = __ldcs(base + q + 7 * NT);
            a0 += __log2f(v0.x) + __log2f(v0.y) + __log2f(v0.z) + __log2f(v0.w);
            a1 += __log2f(v1.x) + __log2f(v1.y) + __log2f(v1.z) + __log2f(v1.w);
            a2 += __log2f(v2.x) + __log2f(v2.y) + __log2f(v2.z) + __log2f(v2.w);
            a3 += __log2f(v3.x) + __log2f(v3.y) + __log2f(v3.z) + __log2f(v3.w);
            a4 += __log2f(v4.x) + __log2f(v4.y) + __log2f(v4.z) + __log2f(v4.w);
            a5 += __log2f(v5.x) + __log2f(v5.y) + __log2f(v5.z) + __log2f(v5.w);
            a6 += __log2f(v6.x) + __log2f(v6.y) + __log2f(v6.z) + __log2f(v6.w);
            a7 += __log2f(v7.x) + __log2f(v7.y) + __log2f(v7.z) + __log2f(v7.w);
        }
        for (; q < qe; q += NT) {
            float4 v = __ldcs(base + q);
            a0 += __log2f(v.x) + __log2f(v.y) + __log2f(v.z) + __log2f(v.w);
        }
        if (bid == nb - 1) {
            for (long long j = (n4 << 2) + threadIdx.x; j < nElem; j += NT)
                a0 += __log2f(__ldg(&srcf[j]));
        }
    } else {
        for (; q + 7 * NT < qe; q += 8 * NT) {
            float4 v0 = __ldcs(base + q);
            float4 v1 = __ldcs(base + q + 1 * NT);
            float4 v2 = __ldcs(base + q + 2 * NT);
            float4 v3 = __ldcs(base + q + 3 * NT);
            float4 v4 = __ldcs(base + q + 4 * NT);
            float4 v5 = __ldcs(base + q + 5 * NT);
            float4 v6 = __ldcs(base + q + 6 * NT);
            float4 v7 = __ldcs(base + q + 7 * NT);
            a0 += v0.x * v0.x + v0.y * v0.y + v0.z * v0.z + v0.w * v0.w;
            a1 += v1.x * v1.x + v1.y * v1.y + v1.z * v1.z + v1.w * v1.w;
            a2 += v2.x * v2.x + v2.y * v2.y + v2.z * v2.z + v2.w * v2.w;
            a3 += v3.x * v3.x + v3.y * v3.y + v3.z * v3.z + v3.w * v3.w;
            a4 += v4.x * v4.x + v4.y * v4.y + v4.z * v4.z + v4.w * v4.w;
            a5 += v5.x * v5.x + v5.y * v5.y + v5.z * v5.z + v5.w * v5.w;
            a6 += v6.x * v6.x + v6.y * v6.y + v6.z * v6.z + v6.w * v6.w;
            a7 += v7.x * v7.x + v7.y * v7.y + v7.z * v7.z + v7.w * v7.w;
        }
        for (; q < qe; q += NT) {
            float4 v = __ldcs(base + q);
            a0 += v.x * v.x + v.y * v.y + v.z * v.z + v.w * v.w;
        }
        if (bid == nb - 1) {
            for (long long j = (n4 << 2) + threadIdx.x; j < nElem; j += NT) {
                float v = __ldg(&srcf[j]);
                a0 += v * v;
            }
        }
    }

    double acc = (((double)a0 + (double)a1) + ((double)a2 + (double)a3))
               + (((double)a4 + (double)a5) + ((double)a6 + (double)a7));
    acc = block_reduce(acc);

    __shared__ bool s_last;
    if (threadIdx.x == 0) {
        if (is_fish) g_part_log[bid] = acc;
        else         g_part_sq[bid]  = acc;
        __threadfence();
        unsigned int prev = atomicAdd(&g_done_count, 1u);
        s_last = (prev == NB - 1);
    }
    __syncthreads();

    // ---- last block to finish performs the final reduction ----
    if (s_last) {
        double a = 0.0, b = 0.0;
        if (threadIdx.x < NB_M) a = g_part_sq[threadIdx.x];
        if (threadIdx.x < NB_F) b = g_part_log[threadIdx.x];
        a = block_reduce(a);
        __syncthreads();
        b = block_reduce(b);
        if (threadIdx.x == 0) {
            const double log2pi = 1.8378770664093453;      // log(2*pi)
            const double logsig = -2.3025850929940456840;  // log(0.1)
            const double inv2s2 = 50.0;                    // 1/(2*0.1^2)
            const double ln2    = 0.6931471805599453;      // log2 -> ln
            double prior_term = (double)(M - 1) *
                (inv2s2 * a + (double)D * (logsig + 0.5 * log2pi));
            double post_term = -0.5 * (double)M * (double)D * log2pi
                               + 0.5 * ln2 * b;
            float loss = (float)(prior_term + post_term);
            for (int k = 0; k < out_size; k++) out[k] = loss;
            g_done_count = 0;      // self-reset for next graph replay
        }
    }
}

extern "C" void kernel_launch(void* const* d_in, const int* in_sizes, int n_in,
                              void* d_out, int out_size)
{
    const float* metamean = (const float*)d_in[0];
    // d_in[1] = means: unused (Mahalanobis term is identically zero)
    const float* fishers  = (const float*)d_in[2];

    const long long D  = (long long)in_sizes[0];
    const long long MD = (long long)in_sizes[2];
    const int M = (int)(MD / D);

    bmp_kernel<<<NB, NT>>>(metamean, fishers, D, MD, M,
                           (float*)d_out, out_size);
}